// round 3
// baseline (speedup 1.0000x reference)
#include <cuda_runtime.h>
#include <math.h>
#include <stdint.h>

#define NN 30000
#define EE 480000
#define EPLUS (EE + NN)
#define NEG 0.2f

// ---------------- scratch (static device globals; no allocation) ----------------
__device__ float g_h [(size_t)NN * 512];
__device__ float g_hn[(size_t)NN * 512];
__device__ float g_hp[(size_t)NN * 512];
__device__ float g_s [NN * 8];
__device__ float g_d [NN * 8];
__device__ int   g_off[NN + 1];
__device__ int   g_cnt[NN];
__device__ int   g_cur[NN];
__device__ int   g_csr[EPLUS];

// ---------------- CSR build ----------------
__global__ void k_init_counts() {
    int i = blockIdx.x * blockDim.x + threadIdx.x;
    if (i < NN) { g_cnt[i] = 1; g_cur[i] = 0; }   // 1 = self loop
}

__global__ void k_count(const int* __restrict__ ei) {
    int i = blockIdx.x * blockDim.x + threadIdx.x;
    if (i < EE) atomicAdd(&g_cnt[ei[EE + i]], 1);
}

__global__ void k_scan() {
    __shared__ int sh[1024];
    __shared__ int carry;
    int tid = threadIdx.x;
    if (tid == 0) { carry = 0; g_off[0] = 0; }
    __syncthreads();
    for (int base = 0; base < NN; base += 1024) {
        int i = base + tid;
        int v = (i < NN) ? g_cnt[i] : 0;
        sh[tid] = v;
        __syncthreads();
        for (int o = 1; o < 1024; o <<= 1) {
            int t = (tid >= o) ? sh[tid - o] : 0;
            __syncthreads();
            sh[tid] += t;
            __syncthreads();
        }
        int inc = sh[tid] + carry;
        if (i < NN) g_off[i + 1] = inc;
        __syncthreads();
        if (tid == 1023) carry = inc;
        __syncthreads();
    }
}

__global__ void k_scatter(const int* __restrict__ ei) {
    int i = blockIdx.x * blockDim.x + threadIdx.x;
    if (i < EE) {
        int dst = ei[EE + i], src = ei[i];
        int p = atomicAdd(&g_cur[dst], 1);
        g_csr[g_off[dst] + p] = src;
    } else if (i < EPLUS) {
        int n = i - EE;
        int p = atomicAdd(&g_cur[n], 1);
        g_csr[g_off[n] + p] = n;
    }
}

// ---------------- input projection: h = relu(x @ W_in + b) ----------------
__global__ void k_input_proj(const float* __restrict__ x, const float* __restrict__ W,
                             const float* __restrict__ b) {
    __shared__ float xs[8][32];
    int j  = threadIdx.x;        // 0..511 (output column)
    int n0 = blockIdx.x * 8;
    if (j < 256) {
        int r = j >> 5, c = j & 31, n = n0 + r;
        xs[r][c] = (n < NN) ? x[n * 32 + c] : 0.f;
    }
    __syncthreads();
    float acc[8] = {0, 0, 0, 0, 0, 0, 0, 0};
#pragma unroll 8
    for (int k = 0; k < 32; k++) {
        float w = W[k * 512 + j];
#pragma unroll
        for (int r = 0; r < 8; r++) acc[r] += xs[r][k] * w;
    }
    float bb = b[j];
#pragma unroll
    for (int r = 0; r < 8; r++) {
        int n = n0 + r;
        if (n < NN) g_h[(size_t)n * 512 + j] = fmaxf(acc[r] + bb, 0.f);
    }
}

// ---------------- fp32 GEMM: hp[M,512] = A[M,512] @ B[512,512] ----------------
__global__ __launch_bounds__(256, 2)
void k_sgemm512(const float* __restrict__ A, const float* __restrict__ B) {
    __shared__ float As[16][128];
    __shared__ float Bs[16][128];
    int tid = threadIdx.x;
    int tr = tid >> 4, tc = tid & 15;
    int rowBase = blockIdx.y * 128;
    int colBase = blockIdx.x * 128;
    float acc[8][8];
#pragma unroll
    for (int i = 0; i < 8; i++)
#pragma unroll
        for (int j = 0; j < 8; j++) acc[i][j] = 0.f;

    int aRow = tid >> 2, aCol = (tid & 3) << 2;
    int bRow = tid >> 5, bCol = (tid & 31) << 2;

    for (int k0 = 0; k0 < 512; k0 += 16) {
#pragma unroll
        for (int s = 0; s < 2; s++) {
            int r = aRow + s * 64;
            int gr = rowBase + r;
            float4 v = make_float4(0.f, 0.f, 0.f, 0.f);
            if (gr < NN) v = *(const float4*)&A[(size_t)gr * 512 + k0 + aCol];
            As[aCol + 0][r] = v.x; As[aCol + 1][r] = v.y;
            As[aCol + 2][r] = v.z; As[aCol + 3][r] = v.w;
        }
#pragma unroll
        for (int s = 0; s < 2; s++) {
            int r = bRow + s * 8;
            *(float4*)&Bs[r][bCol] = *(const float4*)&B[(size_t)(k0 + r) * 512 + colBase + bCol];
        }
        __syncthreads();
#pragma unroll
        for (int k = 0; k < 16; k++) {
            float ra[8], rb[8];
            *(float4*)&ra[0] = *(const float4*)&As[k][tr * 8];
            *(float4*)&ra[4] = *(const float4*)&As[k][tr * 8 + 4];
            *(float4*)&rb[0] = *(const float4*)&Bs[k][tc * 8];
            *(float4*)&rb[4] = *(const float4*)&Bs[k][tc * 8 + 4];
#pragma unroll
            for (int i = 0; i < 8; i++)
#pragma unroll
                for (int j = 0; j < 8; j++)
                    acc[i][j] += ra[i] * rb[j];
        }
        __syncthreads();
    }
#pragma unroll
    for (int i = 0; i < 8; i++) {
        int gr = rowBase + tr * 8 + i;
        if (gr < NN) {
            *(float4*)&g_hp[(size_t)gr * 512 + colBase + tc * 8]     = *(float4*)&acc[i][0];
            *(float4*)&g_hp[(size_t)gr * 512 + colBase + tc * 8 + 4] = *(float4*)&acc[i][4];
        }
    }
}

// ---------------- attention coefficients s,d : [N,8] ----------------
__global__ void k_attn_coef(const float* __restrict__ asrc, const float* __restrict__ adst) {
    int g = blockIdx.x * blockDim.x + threadIdx.x;
    int n = g >> 5, lane = g & 31;
    if (n >= NN) return;
    int c0 = lane * 16;                 // 16 contiguous cols per lane -> head = lane/4
    const float* row = &g_hp[(size_t)n * 512 + c0];
    float ps = 0.f, pd = 0.f;
#pragma unroll
    for (int u = 0; u < 16; u += 4) {
        float4 v = *(const float4*)&row[u];
        float4 a = *(const float4*)&asrc[c0 + u];
        float4 b = *(const float4*)&adst[c0 + u];
        ps += v.x * a.x + v.y * a.y + v.z * a.z + v.w * a.w;
        pd += v.x * b.x + v.y * b.y + v.z * b.z + v.w * b.w;
    }
    ps += __shfl_down_sync(0xffffffffu, ps, 2);
    pd += __shfl_down_sync(0xffffffffu, pd, 2);
    ps += __shfl_down_sync(0xffffffffu, ps, 1);
    pd += __shfl_down_sync(0xffffffffu, pd, 1);
    if ((lane & 3) == 0) {
        g_s[n * 8 + (lane >> 2)] = ps;
        g_d[n * 8 + (lane >> 2)] = pd;
    }
}

// ---------------- GAT aggregation: warp per destination node, no atomics -------
__global__ void k_gat_agg(const float* __restrict__ bias, float* __restrict__ hout) {
    int g = blockIdx.x * blockDim.x + threadIdx.x;
    int n = g >> 5, lane = g & 31;
    if (n >= NN) return;
    int start = g_off[n], end = g_off[n + 1];
    int h8 = lane & 7;                         // this lane's head for e-computation
    float dval = g_d[n * 8 + h8];

    // pass 1: per-head max over neighborhood
    float m = __int_as_float(0xff800000);      // -inf
    for (int j = start + (lane >> 3); j < end; j += 4) {
        int sj = __ldg(&g_csr[j]);
        float e = __ldg(&g_s[sj * 8 + h8]) + dval;
        e = (e > 0.f) ? e : NEG * e;
        m = fmaxf(m, e);
    }
    m = fmaxf(m, __shfl_xor_sync(0xffffffffu, m, 8));
    m = fmaxf(m, __shfl_xor_sync(0xffffffffu, m, 16));

    // pass 2: per-head sum of exp
    float den = 0.f;
    for (int j = start + (lane >> 3); j < end; j += 4) {
        int sj = __ldg(&g_csr[j]);
        float e = __ldg(&g_s[sj * 8 + h8]) + dval;
        e = (e > 0.f) ? e : NEG * e;
        den += __expf(e - m);
    }
    den += __shfl_xor_sync(0xffffffffu, den, 8);
    den += __shfl_xor_sync(0xffffffffu, den, 16);
    float inv = 1.f / (den + 1e-16f);

    // pass 3: weighted gather-accumulate (16 fp32 channels per lane)
    float acc[16];
#pragma unroll
    for (int i = 0; i < 16; i++) acc[i] = 0.f;
    for (int j = start; j < end; j++) {
        int sj = __ldg(&g_csr[j]);
        float e = __ldg(&g_s[sj * 8 + h8]) + dval;
        e = (e > 0.f) ? e : NEG * e;
        float w = __expf(e - m) * inv;         // lane holds weight for head lane&7
        const float4* row = (const float4*)&g_hp[(size_t)sj * 512];
#pragma unroll
        for (int i = 0; i < 4; i++) {
            int hh = i * 2 + (lane >> 4);      // head owning this lane's float4
            float wi = __shfl_sync(0xffffffffu, w, hh);
            float4 v = __ldg(&row[i * 32 + lane]);
            acc[i * 4 + 0] += wi * v.x;
            acc[i * 4 + 1] += wi * v.y;
            acc[i * 4 + 2] += wi * v.z;
            acc[i * 4 + 3] += wi * v.w;
        }
    }
#pragma unroll
    for (int i = 0; i < 4; i++) {
        int col = i * 128 + lane * 4;
        float4 b = *(const float4*)&bias[col];
        float4 o;
        o.x = fmaxf(acc[i * 4 + 0] + b.x, 0.f);
        o.y = fmaxf(acc[i * 4 + 1] + b.y, 0.f);
        o.z = fmaxf(acc[i * 4 + 2] + b.z, 0.f);
        o.w = fmaxf(acc[i * 4 + 3] + b.w, 0.f);
        *(float4*)&hout[(size_t)n * 512 + col] = o;
    }
}

// ---------------- attention_weights head: softmax(h @ W_att + b) ----------------
__global__ void k_attw(const float* __restrict__ h, const float* __restrict__ W,
                       const float* __restrict__ b, float* __restrict__ out) {
    int g = blockIdx.x * blockDim.x + threadIdx.x;
    int n = g >> 5, lane = g & 31;
    if (n >= NN) return;
    int c0 = lane * 16;
    float p[8] = {0, 0, 0, 0, 0, 0, 0, 0};
#pragma unroll
    for (int u = 0; u < 16; u++) {
        float v = h[(size_t)n * 512 + c0 + u];
        float4 w0 = *(const float4*)&W[(c0 + u) * 8];
        float4 w1 = *(const float4*)&W[(c0 + u) * 8 + 4];
        p[0] += v * w0.x; p[1] += v * w0.y; p[2] += v * w0.z; p[3] += v * w0.w;
        p[4] += v * w1.x; p[5] += v * w1.y; p[6] += v * w1.z; p[7] += v * w1.w;
    }
#pragma unroll
    for (int o = 16; o; o >>= 1)
#pragma unroll
        for (int hh = 0; hh < 8; hh++) p[hh] += __shfl_xor_sync(0xffffffffu, p[hh], o);
    if (lane == 0) {
        float mx = -1e30f;
#pragma unroll
        for (int hh = 0; hh < 8; hh++) { p[hh] += b[hh]; mx = fmaxf(mx, p[hh]); }
        float sum = 0.f;
#pragma unroll
        for (int hh = 0; hh < 8; hh++) { p[hh] = __expf(p[hh] - mx); sum += p[hh]; }
        float is = 1.f / sum;
#pragma unroll
        for (int hh = 0; hh < 8; hh++) out[n * 8 + hh] = p[hh] * is;
    }
}

// ---------------- anomaly head: sigmoid(relu(h@W1+b1)@W2+b2) ----------------
__global__ __launch_bounds__(512)
void k_anomaly(const float* __restrict__ h, const float* __restrict__ W1,
               const float* __restrict__ b1, const float* __restrict__ W2,
               const float* __restrict__ b2, float* __restrict__ out) {
    __shared__ float hs[8][516];
    __shared__ float Ws[64][68];
    __shared__ float wsum[16];
    int tid = threadIdx.x;
    int n0 = blockIdx.x * 8;
#pragma unroll
    for (int sidx = 0; sidx < 8; sidx++) {
        int idx = sidx * 512 + tid;
        int rr = idx >> 9, cc = idx & 511;
        int n = n0 + rr;
        hs[rr][cc] = (n < NN) ? h[(size_t)n * 512 + cc] : 0.f;
    }
    int r = tid >> 6, c = tid & 63;
    float acc = 0.f;
    for (int k0 = 0; k0 < 512; k0 += 64) {
        __syncthreads();
#pragma unroll
        for (int sidx = 0; sidx < 8; sidx++) {
            int idx = sidx * 512 + tid;
            int kk = idx >> 6, cc2 = idx & 63;
            Ws[kk][cc2] = W1[(k0 + kk) * 64 + cc2];
        }
        __syncthreads();
#pragma unroll 16
        for (int k = 0; k < 64; k++) acc += hs[r][k0 + k] * Ws[k][c];
    }
    float t = fmaxf(acc + b1[c], 0.f);
    float part = t * W2[c];
#pragma unroll
    for (int o = 16; o; o >>= 1) part += __shfl_xor_sync(0xffffffffu, part, o);
    if ((tid & 31) == 0) wsum[tid >> 5] = part;
    __syncthreads();
    if ((tid & 63) == 0) {
        float sum = wsum[tid >> 5] + wsum[(tid >> 5) + 1];
        int n = n0 + r;
        if (n < NN) out[n] = 1.f / (1.f + __expf(-(sum + b2[0])));
    }
}

// ---------------- helper to get raw pointers to globals (device-side constant) --
__device__ float* dev_h_ptr()  { return g_h;  }

// ---------------- launch: pure kernel launches only ----------------
extern "C" void kernel_launch(void* const* d_in, const int* in_sizes, int n_in,
                              void* d_out, int out_size) {
    const float* x     = (const float*)d_in[0];
    const int*   ei    = (const int*)  d_in[1];
    const float* W_in  = (const float*)d_in[2];
    const float* b_in  = (const float*)d_in[3];
    const float* W_gat = (const float*)d_in[4];
    const float* a_src = (const float*)d_in[5];
    const float* a_dst = (const float*)d_in[6];
    const float* b_gat = (const float*)d_in[7];
    const float* W_att = (const float*)d_in[8];
    const float* b_att = (const float*)d_in[9];
    const float* W_h1  = (const float*)d_in[10];
    const float* b_h1  = (const float*)d_in[11];
    const float* W_h2  = (const float*)d_in[12];
    const float* b_h2  = (const float*)d_in[13];
    float* out = (float*)d_out;

    // CSR by destination (recomputed every call; deterministic work)
    k_init_counts<<<(NN + 255) / 256, 256>>>();
    k_count<<<(EE + 255) / 256, 256>>>(ei);
    k_scan<<<1, 1024>>>();
    k_scatter<<<(EPLUS + 255) / 256, 256>>>(ei);

    // input projection
    k_input_proj<<<(NN + 7) / 8, 512>>>(x, W_in, b_in);

    // 3 GAT layers (ping-pong between g_h and g_hn via static device pointers)
    // Layer inputs/outputs alternate: g_h -> g_hn -> g_h -> g_hn
    dim3 grid(4, (NN + 127) / 128);

    // layer 0: in g_h, out g_hn
    {
        // obtain device pointers at compile time through kernel template args is
        // not possible; instead use small launch-time constants: the GEMM reads A
        // from a pointer arg; g_h/g_hn addresses are resolved by tiny copy kernels
        // below. Simpler: GEMM takes A pointer; we get it from a device-symbol-free
        // approach: pass nullptr markers. To stay allocation- and API-free we use
        // three dedicated wrappers instead.
    }
    // Wrappers defined below via lambdas are not allowed in __global__; instead we
    // exploit that g_h/g_hn are addressable from device code only. So GEMM A input
    // uses an integer selector.
    extern __global__ void k_sgemm_sel(int which, const float* B);
    extern __global__ void k_gat_agg_sel(const float* bias, int outWhich);

    for (int l = 0; l < 3; l++) {
        k_sgemm_sel<<<grid, 256>>>(l & 1, W_gat + (size_t)l * 512 * 512);
        k_attn_coef<<<(NN * 32 + 255) / 256, 256>>>(a_src + l * 512, a_dst + l * 512);
        k_gat_agg_sel<<<(NN * 32 + 255) / 256, 256>>>(b_gat + l * 512, (l & 1) ^ 1);
    }

    // after 3 layers, result is in g_hn (l=2 wrote outWhich=1)
    extern __global__ void k_attw_sel(const float* W, const float* b, float* out);
    extern __global__ void k_anomaly_sel(const float* W1, const float* b1,
                                         const float* W2, const float* b2, float* out);
    k_attw_sel<<<(NN * 32 + 255) / 256, 256>>>(W_att, b_att, out + NN);
    k_anomaly_sel<<<(NN + 7) / 8, 512>>>(W_h1, b_h1, W_h2, b_h2, out);
}

// ---------------- selector wrappers (resolve device-global addresses on GPU) ----
__global__ __launch_bounds__(256, 2)
void k_sgemm_sel(int which, const float* __restrict__ B) {
    const float* A = which ? g_hn : g_h;
    __shared__ float As[16][128];
    __shared__ float Bs[16][128];
    int tid = threadIdx.x;
    int tr = tid >> 4, tc = tid & 15;
    int rowBase = blockIdx.y * 128;
    int colBase = blockIdx.x * 128;
    float acc[8][8];
#pragma unroll
    for (int i = 0; i < 8; i++)
#pragma unroll
        for (int j = 0; j < 8; j++) acc[i][j] = 0.f;
    int aRow = tid >> 2, aCol = (tid & 3) << 2;
    int bRow = tid >> 5, bCol = (tid & 31) << 2;
    for (int k0 = 0; k0 < 512; k0 += 16) {
#pragma unroll
        for (int s = 0; s < 2; s++) {
            int r = aRow + s * 64;
            int gr = rowBase + r;
            float4 v = make_float4(0.f, 0.f, 0.f, 0.f);
            if (gr < NN) v = *(const float4*)&A[(size_t)gr * 512 + k0 + aCol];
            As[aCol + 0][r] = v.x; As[aCol + 1][r] = v.y;
            As[aCol + 2][r] = v.z; As[aCol + 3][r] = v.w;
        }
#pragma unroll
        for (int s = 0; s < 2; s++) {
            int r = bRow + s * 8;
            *(float4*)&Bs[r][bCol] = *(const float4*)&B[(size_t)(k0 + r) * 512 + colBase + bCol];
        }
        __syncthreads();
#pragma unroll
        for (int k = 0; k < 16; k++) {
            float ra[8], rb[8];
            *(float4*)&ra[0] = *(const float4*)&As[k][tr * 8];
            *(float4*)&ra[4] = *(const float4*)&As[k][tr * 8 + 4];
            *(float4*)&rb[0] = *(const float4*)&Bs[k][tc * 8];
            *(float4*)&rb[4] = *(const float4*)&Bs[k][tc * 8 + 4];
#pragma unroll
            for (int i = 0; i < 8; i++)
#pragma unroll
                for (int j = 0; j < 8; j++)
                    acc[i][j] += ra[i] * rb[j];
        }
        __syncthreads();
    }
#pragma unroll
    for (int i = 0; i < 8; i++) {
        int gr = rowBase + tr * 8 + i;
        if (gr < NN) {
            *(float4*)&g_hp[(size_t)gr * 512 + colBase + tc * 8]     = *(float4*)&acc[i][0];
            *(float4*)&g_hp[(size_t)gr * 512 + colBase + tc * 8 + 4] = *(float4*)&acc[i][4];
        }
    }
}

__global__ void k_gat_agg_sel(const float* __restrict__ bias, int outWhich) {
    float* hout = outWhich ? g_hn : g_h;
    int g = blockIdx.x * blockDim.x + threadIdx.x;
    int n = g >> 5, lane = g & 31;
    if (n >= NN) return;
    int start = g_off[n], end = g_off[n + 1];
    int h8 = lane & 7;
    float dval = g_d[n * 8 + h8];
    float m = __int_as_float(0xff800000);
    for (int j = start + (lane >> 3); j < end; j += 4) {
        int sj = __ldg(&g_csr[j]);
        float e = __ldg(&g_s[sj * 8 + h8]) + dval;
        e = (e > 0.f) ? e : NEG * e;
        m = fmaxf(m, e);
    }
    m = fmaxf(m, __shfl_xor_sync(0xffffffffu, m, 8));
    m = fmaxf(m, __shfl_xor_sync(0xffffffffu, m, 16));
    float den = 0.f;
    for (int j = start + (lane >> 3); j < end; j += 4) {
        int sj = __ldg(&g_csr[j]);
        float e = __ldg(&g_s[sj * 8 + h8]) + dval;
        e = (e > 0.f) ? e : NEG * e;
        den += __expf(e - m);
    }
    den += __shfl_xor_sync(0xffffffffu, den, 8);
    den += __shfl_xor_sync(0xffffffffu, den, 16);
    float inv = 1.f / (den + 1e-16f);
    float acc[16];
#pragma unroll
    for (int i = 0; i < 16; i++) acc[i] = 0.f;
    for (int j = start; j < end; j++) {
        int sj = __ldg(&g_csr[j]);
        float e = __ldg(&g_s[sj * 8 + h8]) + dval;
        e = (e > 0.f) ? e : NEG * e;
        float w = __expf(e - m) * inv;
        const float4* row = (const float4*)&g_hp[(size_t)sj * 512];
#pragma unroll
        for (int i = 0; i < 4; i++) {
            int hh = i * 2 + (lane >> 4);
            float wi = __shfl_sync(0xffffffffu, w, hh);
            float4 v = __ldg(&row[i * 32 + lane]);
            acc[i * 4 + 0] += wi * v.x;
            acc[i * 4 + 1] += wi * v.y;
            acc[i * 4 + 2] += wi * v.z;
            acc[i * 4 + 3] += wi * v.w;
        }
    }
#pragma unroll
    for (int i = 0; i < 4; i++) {
        int col = i * 128 + lane * 4;
        float4 b = *(const float4*)&bias[col];
        float4 o;
        o.x = fmaxf(acc[i * 4 + 0] + b.x, 0.f);
        o.y = fmaxf(acc[i * 4 + 1] + b.y, 0.f);
        o.z = fmaxf(acc[i * 4 + 2] + b.z, 0.f);
        o.w = fmaxf(acc[i * 4 + 3] + b.w, 0.f);
        *(float4*)&hout[(size_t)n * 512 + col] = o;
    }
}

__global__ void k_attw_sel(const float* __restrict__ W, const float* __restrict__ b,
                           float* __restrict__ out) {
    const float* h = g_hn;   // final layer output
    int g = blockIdx.x * blockDim.x + threadIdx.x;
    int n = g >> 5, lane = g & 31;
    if (n >= NN) return;
    int c0 = lane * 16;
    float p[8] = {0, 0, 0, 0, 0, 0, 0, 0};
#pragma unroll
    for (int u = 0; u < 16; u++) {
        float v = h[(size_t)n * 512 + c0 + u];
        float4 w0 = *(const float4*)&W[(c0 + u) * 8];
        float4 w1 = *(const float4*)&W[(c0 + u) * 8 + 4];
        p[0] += v * w0.x; p[1] += v * w0.y; p[2] += v * w0.z; p[3] += v * w0.w;
        p[4] += v * w1.x; p[5] += v * w1.y; p[6] += v * w1.z; p[7] += v * w1.w;
    }
#pragma unroll
    for (int o = 16; o; o >>= 1)
#pragma unroll
        for (int hh = 0; hh < 8; hh++) p[hh] += __shfl_xor_sync(0xffffffffu, p[hh], o);
    if (lane == 0) {
        float mx = -1e30f;
#pragma unroll
        for (int hh = 0; hh < 8; hh++) { p[hh] += b[hh]; mx = fmaxf(mx, p[hh]); }
        float sum = 0.f;
#pragma unroll
        for (int hh = 0; hh < 8; hh++) { p[hh] = __expf(p[hh] - mx); sum += p[hh]; }
        float is = 1.f / sum;
#pragma unroll
        for (int hh = 0; hh < 8; hh++) out[n * 8 + hh] = p[hh] * is;
    }
}

__global__ __launch_bounds__(512)
void k_anomaly_sel(const float* __restrict__ W1, const float* __restrict__ b1,
                   const float* __restrict__ W2, const float* __restrict__ b2,
                   float* __restrict__ out) {
    const float* h = g_hn;   // final layer output
    __shared__ float hs[8][516];
    __shared__ float Ws[64][68];
    __shared__ float wsum[16];
    int tid = threadIdx.x;
    int n0 = blockIdx.x * 8;
#pragma unroll
    for (int sidx = 0; sidx < 8; sidx++) {
        int idx = sidx * 512 + tid;
        int rr = idx >> 9, cc = idx & 511;
        int n = n0 + rr;
        hs[rr][cc] = (n < NN) ? h[(size_t)n * 512 + cc] : 0.f;
    }
    int r = tid >> 6, c = tid & 63;
    float acc = 0.f;
    for (int k0 = 0; k0 < 512; k0 += 64) {
        __syncthreads();
#pragma unroll
        for (int sidx = 0; sidx < 8; sidx++) {
            int idx = sidx * 512 + tid;
            int kk = idx >> 6, cc2 = idx & 63;
            Ws[kk][cc2] = W1[(k0 + kk) * 64 + cc2];
        }
        __syncthreads();
#pragma unroll 16
        for (int k = 0; k < 64; k++) acc += hs[r][k0 + k] * Ws[k][c];
    }
    float t = fmaxf(acc + b1[c], 0.f);
    float part = t * W2[c];
#pragma unroll
    for (int o = 16; o; o >>= 1) part += __shfl_xor_sync(0xffffffffu, part, o);
    if ((tid & 31) == 0) wsum[tid >> 5] = part;
    __syncthreads();
    if ((tid & 63) == 0) {
        float sum = wsum[tid >> 5] + wsum[(tid >> 5) + 1];
        int n = n0 + r;
        if (n < NN) out[n] = 1.f / (1.f + __expf(-(sum + b2[0])));
    }
}

// round 4
// speedup vs baseline: 1.1423x; 1.1423x over previous
#include <cuda_runtime.h>
#include <math.h>
#include <stdint.h>

#define NN 30000
#define EE 480000
#define EPLUS (EE + NN)
#define NEG 0.2f

// ---------------- scratch (static device globals; no allocation) ----------------
__device__ float g_h [(size_t)NN * 512];
__device__ float g_hn[(size_t)NN * 512];
__device__ float g_hp[(size_t)NN * 512];
__device__ float g_s [NN * 8];
__device__ float g_d [NN * 8];
__device__ int   g_off[NN + 1];
__device__ int   g_cnt[NN];
__device__ int   g_cur[NN];
__device__ int   g_csr[EPLUS];

// ---------------- CSR build ----------------
__global__ void k_init_counts() {
    int i = blockIdx.x * blockDim.x + threadIdx.x;
    if (i < NN) { g_cnt[i] = 1; g_cur[i] = 0; }   // 1 = self loop
}

__global__ void k_count(const int* __restrict__ ei) {
    int i = blockIdx.x * blockDim.x + threadIdx.x;
    if (i < EE) atomicAdd(&g_cnt[ei[EE + i]], 1);
}

__global__ void k_scan() {
    __shared__ int sh[1024];
    __shared__ int carry;
    int tid = threadIdx.x;
    if (tid == 0) { carry = 0; g_off[0] = 0; }
    __syncthreads();
    for (int base = 0; base < NN; base += 1024) {
        int i = base + tid;
        int v = (i < NN) ? g_cnt[i] : 0;
        sh[tid] = v;
        __syncthreads();
        for (int o = 1; o < 1024; o <<= 1) {
            int t = (tid >= o) ? sh[tid - o] : 0;
            __syncthreads();
            sh[tid] += t;
            __syncthreads();
        }
        int inc = sh[tid] + carry;
        if (i < NN) g_off[i + 1] = inc;
        __syncthreads();
        if (tid == 1023) carry = inc;
        __syncthreads();
    }
}

__global__ void k_scatter(const int* __restrict__ ei) {
    int i = blockIdx.x * blockDim.x + threadIdx.x;
    if (i < EE) {
        int dst = ei[EE + i], src = ei[i];
        int p = atomicAdd(&g_cur[dst], 1);
        g_csr[g_off[dst] + p] = src;
    } else if (i < EPLUS) {
        int n = i - EE;
        int p = atomicAdd(&g_cur[n], 1);
        g_csr[g_off[n] + p] = n;
    }
}

// ---------------- input projection: h = relu(x @ W_in + b) ----------------
__global__ void k_input_proj(const float* __restrict__ x, const float* __restrict__ W,
                             const float* __restrict__ b) {
    __shared__ float xs[8][32];
    int j  = threadIdx.x;        // 0..511 (output column)
    int n0 = blockIdx.x * 8;
    if (j < 256) {
        int r = j >> 5, c = j & 31, n = n0 + r;
        xs[r][c] = (n < NN) ? x[n * 32 + c] : 0.f;
    }
    __syncthreads();
    float acc[8] = {0, 0, 0, 0, 0, 0, 0, 0};
#pragma unroll 8
    for (int k = 0; k < 32; k++) {
        float w = W[k * 512 + j];
#pragma unroll
        for (int r = 0; r < 8; r++) acc[r] += xs[r][k] * w;
    }
    float bb = b[j];
#pragma unroll
    for (int r = 0; r < 8; r++) {
        int n = n0 + r;
        if (n < NN) g_h[(size_t)n * 512 + j] = fmaxf(acc[r] + bb, 0.f);
    }
}

// ---------------- tf32 helpers ----------------
__device__ __forceinline__ uint32_t f2tf32(float f) {
    uint32_t r;
    asm("cvt.rna.tf32.f32 %0, %1;" : "=r"(r) : "f"(f));
    return r;
}

__device__ __forceinline__ void mma_tf32(float* c, const uint32_t* a, const uint32_t* b) {
    asm volatile(
        "mma.sync.aligned.m16n8k8.row.col.f32.tf32.tf32.f32 "
        "{%0,%1,%2,%3}, {%4,%5,%6,%7}, {%8,%9}, {%0,%1,%2,%3};\n"
        : "+f"(c[0]), "+f"(c[1]), "+f"(c[2]), "+f"(c[3])
        : "r"(a[0]), "r"(a[1]), "r"(a[2]), "r"(a[3]), "r"(b[0]), "r"(b[1]));
}

// ---------------- 3xTF32 tensor-core GEMM: g_hp = A[NN,512] @ B[512,512] --------
// CTA tile 128x128, 8 warps (2x4), warp tile 64x32, kblock 16.
#define APAD 20
#define BPAD 136
__global__ __launch_bounds__(256, 2)
void k_gemm_tf32(int which, const float* __restrict__ B) {
    const float* A = which ? g_hn : g_h;
    __shared__ uint32_t As_hi[128][APAD];
    __shared__ uint32_t As_lo[128][APAD];
    __shared__ uint32_t Bs_hi[16][BPAD];
    __shared__ uint32_t Bs_lo[16][BPAD];

    int tid  = threadIdx.x;
    int lane = tid & 31;
    int warp = tid >> 5;
    int warp_m = (warp & 1) * 64;
    int warp_n = (warp >> 1) * 32;
    int rowBase = blockIdx.y * 128;
    int colBase = blockIdx.x * 128;

    float acc[4][4][4];
#pragma unroll
    for (int i = 0; i < 4; i++)
#pragma unroll
        for (int j = 0; j < 4; j++)
#pragma unroll
            for (int k = 0; k < 4; k++) acc[i][j][k] = 0.f;

    // loader indices
    int aRow = tid >> 2;              // 0..63 (+64 via s)
    int aKg  = (tid & 3) << 2;        // 0,4,8,12
    int bK   = tid >> 5;              // 0..7 (+8 via s)
    int bCol = (tid & 31) << 2;       // 0..124

    for (int k0 = 0; k0 < 512; k0 += 16) {
#pragma unroll
        for (int s = 0; s < 2; s++) {
            int r  = aRow + s * 64;
            int gr = rowBase + r;
            float4 v = make_float4(0.f, 0.f, 0.f, 0.f);
            if (gr < NN) v = *(const float4*)&A[(size_t)gr * 512 + k0 + aKg];
            uint32_t h0 = f2tf32(v.x), h1 = f2tf32(v.y), h2 = f2tf32(v.z), h3 = f2tf32(v.w);
            uint32_t l0 = f2tf32(v.x - __uint_as_float(h0));
            uint32_t l1 = f2tf32(v.y - __uint_as_float(h1));
            uint32_t l2 = f2tf32(v.z - __uint_as_float(h2));
            uint32_t l3 = f2tf32(v.w - __uint_as_float(h3));
            *(uint4*)&As_hi[r][aKg] = make_uint4(h0, h1, h2, h3);
            *(uint4*)&As_lo[r][aKg] = make_uint4(l0, l1, l2, l3);
        }
#pragma unroll
        for (int s = 0; s < 2; s++) {
            int kr = bK + s * 8;
            float4 v = *(const float4*)&B[(size_t)(k0 + kr) * 512 + colBase + bCol];
            uint32_t h0 = f2tf32(v.x), h1 = f2tf32(v.y), h2 = f2tf32(v.z), h3 = f2tf32(v.w);
            uint32_t l0 = f2tf32(v.x - __uint_as_float(h0));
            uint32_t l1 = f2tf32(v.y - __uint_as_float(h1));
            uint32_t l2 = f2tf32(v.z - __uint_as_float(h2));
            uint32_t l3 = f2tf32(v.w - __uint_as_float(h3));
            *(uint4*)&Bs_hi[kr][bCol] = make_uint4(h0, h1, h2, h3);
            *(uint4*)&Bs_lo[kr][bCol] = make_uint4(l0, l1, l2, l3);
        }
        __syncthreads();

#pragma unroll
        for (int k8 = 0; k8 < 16; k8 += 8) {
            uint32_t bh[4][2], bl[4][2];
#pragma unroll
            for (int nt = 0; nt < 4; nt++) {
                int cc = warp_n + nt * 8 + (lane >> 2);
                bh[nt][0] = Bs_hi[k8 + (lane & 3)][cc];
                bh[nt][1] = Bs_hi[k8 + 4 + (lane & 3)][cc];
                bl[nt][0] = Bs_lo[k8 + (lane & 3)][cc];
                bl[nt][1] = Bs_lo[k8 + 4 + (lane & 3)][cc];
            }
#pragma unroll
            for (int mt = 0; mt < 4; mt++) {
                int r0 = warp_m + mt * 16 + (lane >> 2);
                uint32_t ah[4], al[4];
                ah[0] = As_hi[r0    ][k8 + (lane & 3)];
                ah[1] = As_hi[r0 + 8][k8 + (lane & 3)];
                ah[2] = As_hi[r0    ][k8 + 4 + (lane & 3)];
                ah[3] = As_hi[r0 + 8][k8 + 4 + (lane & 3)];
                al[0] = As_lo[r0    ][k8 + (lane & 3)];
                al[1] = As_lo[r0 + 8][k8 + (lane & 3)];
                al[2] = As_lo[r0    ][k8 + 4 + (lane & 3)];
                al[3] = As_lo[r0 + 8][k8 + 4 + (lane & 3)];
#pragma unroll
                for (int nt = 0; nt < 4; nt++) {
                    mma_tf32(acc[mt][nt], ah, bh[nt]);   // hi*hi
                    mma_tf32(acc[mt][nt], ah, bl[nt]);   // hi*lo
                    mma_tf32(acc[mt][nt], al, bh[nt]);   // lo*hi
                }
            }
        }
        __syncthreads();
    }

    // epilogue
#pragma unroll
    for (int mt = 0; mt < 4; mt++) {
        int gr0 = rowBase + warp_m + mt * 16 + (lane >> 2);
#pragma unroll
        for (int nt = 0; nt < 4; nt++) {
            int col = colBase + warp_n + nt * 8 + (lane & 3) * 2;
            if (gr0 < NN)
                *(float2*)&g_hp[(size_t)gr0 * 512 + col] = make_float2(acc[mt][nt][0], acc[mt][nt][1]);
            if (gr0 + 8 < NN)
                *(float2*)&g_hp[(size_t)(gr0 + 8) * 512 + col] = make_float2(acc[mt][nt][2], acc[mt][nt][3]);
        }
    }
}

// ---------------- attention coefficients s,d : [N,8] ----------------
__global__ void k_attn_coef(const float* __restrict__ asrc, const float* __restrict__ adst) {
    int g = blockIdx.x * blockDim.x + threadIdx.x;
    int n = g >> 5, lane = g & 31;
    if (n >= NN) return;
    int c0 = lane * 16;                 // 16 contiguous cols per lane -> head = lane/4
    const float* row = &g_hp[(size_t)n * 512 + c0];
    float ps = 0.f, pd = 0.f;
#pragma unroll
    for (int u = 0; u < 16; u += 4) {
        float4 v = *(const float4*)&row[u];
        float4 a = *(const float4*)&asrc[c0 + u];
        float4 b = *(const float4*)&adst[c0 + u];
        ps += v.x * a.x + v.y * a.y + v.z * a.z + v.w * a.w;
        pd += v.x * b.x + v.y * b.y + v.z * b.z + v.w * b.w;
    }
    ps += __shfl_down_sync(0xffffffffu, ps, 2);
    pd += __shfl_down_sync(0xffffffffu, pd, 2);
    ps += __shfl_down_sync(0xffffffffu, ps, 1);
    pd += __shfl_down_sync(0xffffffffu, pd, 1);
    if ((lane & 3) == 0) {
        g_s[n * 8 + (lane >> 2)] = ps;
        g_d[n * 8 + (lane >> 2)] = pd;
    }
}

// ---------------- GAT aggregation: warp per destination node, no atomics -------
__global__ void k_gat_agg_sel(const float* __restrict__ bias, int outWhich) {
    float* hout = outWhich ? g_hn : g_h;
    int g = blockIdx.x * blockDim.x + threadIdx.x;
    int n = g >> 5, lane = g & 31;
    if (n >= NN) return;
    int start = g_off[n], end = g_off[n + 1];
    int h8 = lane & 7;
    float dval = g_d[n * 8 + h8];
    float m = __int_as_float(0xff800000);
    for (int j = start + (lane >> 3); j < end; j += 4) {
        int sj = __ldg(&g_csr[j]);
        float e = __ldg(&g_s[sj * 8 + h8]) + dval;
        e = (e > 0.f) ? e : NEG * e;
        m = fmaxf(m, e);
    }
    m = fmaxf(m, __shfl_xor_sync(0xffffffffu, m, 8));
    m = fmaxf(m, __shfl_xor_sync(0xffffffffu, m, 16));
    float den = 0.f;
    for (int j = start + (lane >> 3); j < end; j += 4) {
        int sj = __ldg(&g_csr[j]);
        float e = __ldg(&g_s[sj * 8 + h8]) + dval;
        e = (e > 0.f) ? e : NEG * e;
        den += __expf(e - m);
    }
    den += __shfl_xor_sync(0xffffffffu, den, 8);
    den += __shfl_xor_sync(0xffffffffu, den, 16);
    float inv = 1.f / (den + 1e-16f);
    float acc[16];
#pragma unroll
    for (int i = 0; i < 16; i++) acc[i] = 0.f;
    for (int j = start; j < end; j++) {
        int sj = __ldg(&g_csr[j]);
        float e = __ldg(&g_s[sj * 8 + h8]) + dval;
        e = (e > 0.f) ? e : NEG * e;
        float w = __expf(e - m) * inv;
        const float4* row = (const float4*)&g_hp[(size_t)sj * 512];
#pragma unroll
        for (int i = 0; i < 4; i++) {
            int hh = i * 2 + (lane >> 4);
            float wi = __shfl_sync(0xffffffffu, w, hh);
            float4 v = __ldg(&row[i * 32 + lane]);
            acc[i * 4 + 0] += wi * v.x;
            acc[i * 4 + 1] += wi * v.y;
            acc[i * 4 + 2] += wi * v.z;
            acc[i * 4 + 3] += wi * v.w;
        }
    }
#pragma unroll
    for (int i = 0; i < 4; i++) {
        int col = i * 128 + lane * 4;
        float4 b = *(const float4*)&bias[col];
        float4 o;
        o.x = fmaxf(acc[i * 4 + 0] + b.x, 0.f);
        o.y = fmaxf(acc[i * 4 + 1] + b.y, 0.f);
        o.z = fmaxf(acc[i * 4 + 2] + b.z, 0.f);
        o.w = fmaxf(acc[i * 4 + 3] + b.w, 0.f);
        *(float4*)&hout[(size_t)n * 512 + col] = o;
    }
}

// ---------------- attention_weights head: softmax(h @ W_att + b) ----------------
__global__ void k_attw_sel(const float* __restrict__ W, const float* __restrict__ b,
                           float* __restrict__ out) {
    const float* h = g_hn;   // final layer output
    int g = blockIdx.x * blockDim.x + threadIdx.x;
    int n = g >> 5, lane = g & 31;
    if (n >= NN) return;
    int c0 = lane * 16;
    float p[8] = {0, 0, 0, 0, 0, 0, 0, 0};
#pragma unroll
    for (int u = 0; u < 16; u++) {
        float v = h[(size_t)n * 512 + c0 + u];
        float4 w0 = *(const float4*)&W[(c0 + u) * 8];
        float4 w1 = *(const float4*)&W[(c0 + u) * 8 + 4];
        p[0] += v * w0.x; p[1] += v * w0.y; p[2] += v * w0.z; p[3] += v * w0.w;
        p[4] += v * w1.x; p[5] += v * w1.y; p[6] += v * w1.z; p[7] += v * w1.w;
    }
#pragma unroll
    for (int o = 16; o; o >>= 1)
#pragma unroll
        for (int hh = 0; hh < 8; hh++) p[hh] += __shfl_xor_sync(0xffffffffu, p[hh], o);
    if (lane == 0) {
        float mx = -1e30f;
#pragma unroll
        for (int hh = 0; hh < 8; hh++) { p[hh] += b[hh]; mx = fmaxf(mx, p[hh]); }
        float sum = 0.f;
#pragma unroll
        for (int hh = 0; hh < 8; hh++) { p[hh] = __expf(p[hh] - mx); sum += p[hh]; }
        float is = 1.f / sum;
#pragma unroll
        for (int hh = 0; hh < 8; hh++) out[n * 8 + hh] = p[hh] * is;
    }
}

// ---------------- anomaly head: sigmoid(relu(h@W1+b1)@W2+b2) ----------------
__global__ __launch_bounds__(512)
void k_anomaly_sel(const float* __restrict__ W1, const float* __restrict__ b1,
                   const float* __restrict__ W2, const float* __restrict__ b2,
                   float* __restrict__ out) {
    const float* h = g_hn;   // final layer output
    __shared__ float hs[8][516];
    __shared__ float Ws[64][68];
    __shared__ float wsum[16];
    int tid = threadIdx.x;
    int n0 = blockIdx.x * 8;
#pragma unroll
    for (int sidx = 0; sidx < 8; sidx++) {
        int idx = sidx * 512 + tid;
        int rr = idx >> 9, cc = idx & 511;
        int n = n0 + rr;
        hs[rr][cc] = (n < NN) ? h[(size_t)n * 512 + cc] : 0.f;
    }
    int r = tid >> 6, c = tid & 63;
    float acc = 0.f;
    for (int k0 = 0; k0 < 512; k0 += 64) {
        __syncthreads();
#pragma unroll
        for (int sidx = 0; sidx < 8; sidx++) {
            int idx = sidx * 512 + tid;
            int kk = idx >> 6, cc2 = idx & 63;
            Ws[kk][cc2] = W1[(k0 + kk) * 64 + cc2];
        }
        __syncthreads();
#pragma unroll 16
        for (int k = 0; k < 64; k++) acc += hs[r][k0 + k] * Ws[k][c];
    }
    float t = fmaxf(acc + b1[c], 0.f);
    float part = t * W2[c];
#pragma unroll
    for (int o = 16; o; o >>= 1) part += __shfl_xor_sync(0xffffffffu, part, o);
    if ((tid & 31) == 0) wsum[tid >> 5] = part;
    __syncthreads();
    if ((tid & 63) == 0) {
        float sum = wsum[tid >> 5] + wsum[(tid >> 5) + 1];
        int n = n0 + r;
        if (n < NN) out[n] = 1.f / (1.f + __expf(-(sum + b2[0])));
    }
}

// ---------------- launch: pure kernel launches only ----------------
extern "C" void kernel_launch(void* const* d_in, const int* in_sizes, int n_in,
                              void* d_out, int out_size) {
    const float* x     = (const float*)d_in[0];
    const int*   ei    = (const int*)  d_in[1];
    const float* W_in  = (const float*)d_in[2];
    const float* b_in  = (const float*)d_in[3];
    const float* W_gat = (const float*)d_in[4];
    const float* a_src = (const float*)d_in[5];
    const float* a_dst = (const float*)d_in[6];
    const float* b_gat = (const float*)d_in[7];
    const float* W_att = (const float*)d_in[8];
    const float* b_att = (const float*)d_in[9];
    const float* W_h1  = (const float*)d_in[10];
    const float* b_h1  = (const float*)d_in[11];
    const float* W_h2  = (const float*)d_in[12];
    const float* b_h2  = (const float*)d_in[13];
    float* out = (float*)d_out;

    // CSR by destination (recomputed every call; deterministic work)
    k_init_counts<<<(NN + 255) / 256, 256>>>();
    k_count<<<(EE + 255) / 256, 256>>>(ei);
    k_scan<<<1, 1024>>>();
    k_scatter<<<(EPLUS + 255) / 256, 256>>>(ei);

    // input projection
    k_input_proj<<<(NN + 7) / 8, 512>>>(x, W_in, b_in);

    // 3 GAT layers (ping-pong g_h <-> g_hn; selector picks device-global)
    dim3 grid(4, (NN + 127) / 128);
    for (int l = 0; l < 3; l++) {
        k_gemm_tf32<<<grid, 256>>>(l & 1, W_gat + (size_t)l * 512 * 512);
        k_attn_coef<<<(NN * 32 + 255) / 256, 256>>>(a_src + l * 512, a_dst + l * 512);
        k_gat_agg_sel<<<(NN * 32 + 255) / 256, 256>>>(b_gat + l * 512, (l & 1) ^ 1);
    }

    // heads: out[0:N) = anomaly scores, out[N:N+8N) = attention weights
    k_attw_sel<<<(NN * 32 + 255) / 256, 256>>>(W_att, b_att, out + NN);
    k_anomaly_sel<<<(NN + 7) / 8, 512>>>(W_h1, b_h1, W_h2, b_h2, out);
}

// round 5
// speedup vs baseline: 1.1923x; 1.0438x over previous
#include <cuda_runtime.h>
#include <math.h>
#include <stdint.h>

#define NN 30000
#define EE 480000
#define EPLUS (EE + NN)
#define NEG 0.2f

// ---------------- scratch (static device globals; no allocation) ----------------
__device__ float    g_hn[(size_t)NN * 512];   // final-layer f32 output (heads input)
__device__ float    g_hp[(size_t)NN * 512];   // per-layer GEMM output
__device__ uint32_t g_Ahi[(size_t)NN * 512];  // activations, tf32 hi part
__device__ uint32_t g_Alo[(size_t)NN * 512];  // activations, tf32 lo part
__device__ uint32_t g_Bhi[512 * 512];
__device__ uint32_t g_Blo[512 * 512];
__device__ float    g_s [NN * 8];
__device__ float    g_d [NN * 8];
__device__ int      g_off[NN + 1];
__device__ int      g_cnt[NN];
__device__ int      g_cur[NN];
__device__ int      g_csr[EPLUS];

// ---------------- small helpers ----------------
__device__ __forceinline__ uint32_t f2tf32(float f) {
    uint32_t r;
    asm("cvt.rna.tf32.f32 %0, %1;" : "=r"(r) : "f"(f));
    return r;
}
__device__ __forceinline__ void split_tf32(float f, uint32_t& hi, uint32_t& lo) {
    hi = f2tf32(f);
    lo = f2tf32(f - __uint_as_float(hi));
}
__device__ __forceinline__ void mma_tf32(float* c, const uint32_t* a, const uint32_t* b) {
    asm volatile(
        "mma.sync.aligned.m16n8k8.row.col.f32.tf32.tf32.f32 "
        "{%0,%1,%2,%3}, {%4,%5,%6,%7}, {%8,%9}, {%0,%1,%2,%3};\n"
        : "+f"(c[0]), "+f"(c[1]), "+f"(c[2]), "+f"(c[3])
        : "r"(a[0]), "r"(a[1]), "r"(a[2]), "r"(a[3]), "r"(b[0]), "r"(b[1]));
}
__device__ __forceinline__ uint32_t smem_u32(const void* p) {
    return (uint32_t)__cvta_generic_to_shared(p);
}
__device__ __forceinline__ void cp_async16(uint32_t dst, const void* src, int src_bytes) {
    asm volatile("cp.async.cg.shared.global [%0], [%1], 16, %2;\n"
                 :: "r"(dst), "l"(src), "r"(src_bytes));
}
__device__ __forceinline__ void cp_commit() { asm volatile("cp.async.commit_group;\n"); }
template <int N>
__device__ __forceinline__ void cp_wait() { asm volatile("cp.async.wait_group %0;\n" :: "n"(N)); }

// ---------------- CSR build ----------------
__global__ void k_init_counts() {
    int i = blockIdx.x * blockDim.x + threadIdx.x;
    if (i < NN) { g_cnt[i] = 1; g_cur[i] = 0; }   // 1 = self loop
}

__global__ void k_count(const int* __restrict__ ei) {
    int i = blockIdx.x * blockDim.x + threadIdx.x;
    if (i < EE) atomicAdd(&g_cnt[ei[EE + i]], 1);
}

__global__ void k_scan() {
    __shared__ int sh[1024];
    __shared__ int carry;
    int tid = threadIdx.x;
    if (tid == 0) { carry = 0; g_off[0] = 0; }
    __syncthreads();
    for (int base = 0; base < NN; base += 1024) {
        int i = base + tid;
        int v = (i < NN) ? g_cnt[i] : 0;
        sh[tid] = v;
        __syncthreads();
        for (int o = 1; o < 1024; o <<= 1) {
            int t = (tid >= o) ? sh[tid - o] : 0;
            __syncthreads();
            sh[tid] += t;
            __syncthreads();
        }
        int inc = sh[tid] + carry;
        if (i < NN) g_off[i + 1] = inc;
        __syncthreads();
        if (tid == 1023) carry = inc;
        __syncthreads();
    }
}

__global__ void k_scatter(const int* __restrict__ ei) {
    int i = blockIdx.x * blockDim.x + threadIdx.x;
    if (i < EE) {
        int dst = ei[EE + i], src = ei[i];
        int p = atomicAdd(&g_cur[dst], 1);
        g_csr[g_off[dst] + p] = src;
    } else if (i < EPLUS) {
        int n = i - EE;
        int p = atomicAdd(&g_cur[n], 1);
        g_csr[g_off[n] + p] = n;
    }
}

// ---------------- input projection: relu(x @ W_in + b) -> hi/lo ----------------
__global__ void k_input_proj(const float* __restrict__ x, const float* __restrict__ W,
                             const float* __restrict__ b) {
    __shared__ float xs[8][32];
    int j  = threadIdx.x;        // 0..511 (output column)
    int n0 = blockIdx.x * 8;
    if (j < 256) {
        int r = j >> 5, c = j & 31, n = n0 + r;
        xs[r][c] = (n < NN) ? x[n * 32 + c] : 0.f;
    }
    __syncthreads();
    float acc[8] = {0, 0, 0, 0, 0, 0, 0, 0};
#pragma unroll 8
    for (int k = 0; k < 32; k++) {
        float w = W[k * 512 + j];
#pragma unroll
        for (int r = 0; r < 8; r++) acc[r] += xs[r][k] * w;
    }
    float bb = b[j];
#pragma unroll
    for (int r = 0; r < 8; r++) {
        int n = n0 + r;
        if (n < NN) {
            float v = fmaxf(acc[r] + bb, 0.f);
            uint32_t hi, lo;
            split_tf32(v, hi, lo);
            g_Ahi[(size_t)n * 512 + j] = hi;
            g_Alo[(size_t)n * 512 + j] = lo;
        }
    }
}

// ---------------- weight split: B -> Bhi/Blo ----------------
__global__ void k_convB(const float* __restrict__ B) {
    int i = (blockIdx.x * blockDim.x + threadIdx.x) * 4;
    float4 v = *(const float4*)&B[i];
    uint4 h, l;
    split_tf32(v.x, h.x, l.x);
    split_tf32(v.y, h.y, l.y);
    split_tf32(v.z, h.z, l.z);
    split_tf32(v.w, h.w, l.w);
    *(uint4*)&g_Bhi[i] = h;
    *(uint4*)&g_Blo[i] = l;
}

// ---------------- 3xTF32 double-buffered GEMM: g_hp = A @ B ----------------
// smem buffer layout (uint32 units), per buffer (9472 uints = 37888 B):
//   [0,2560)       As_hi  [128][20]
//   [2560,5120)    As_lo  [128][20]
//   [5120,7296)    Bs_hi  [16][136]
//   [7296,9472)    Bs_lo  [16][136]
#define GEMM_BUF 9472

__device__ __forceinline__ void gemm_stage(uint32_t* sm, int buf, int k0,
                                           int rowBase, int colBase,
                                           int aRow, int aKg, int bK, int bCol) {
    uint32_t base = buf * GEMM_BUF;
#pragma unroll
    for (int s = 0; s < 2; s++) {
        int r  = aRow + s * 64;
        int gr = rowBase + r;
        int sz = (gr < NN) ? 16 : 0;
        size_t off = (size_t)(gr < NN ? gr : NN - 1) * 512 + k0 + aKg;
        cp_async16(smem_u32(&sm[base + r * 20 + aKg]),        &g_Ahi[off], sz);
        cp_async16(smem_u32(&sm[base + 2560 + r * 20 + aKg]), &g_Alo[off], sz);
    }
#pragma unroll
    for (int s = 0; s < 2; s++) {
        int kr = bK + s * 8;
        size_t off = (size_t)(k0 + kr) * 512 + colBase + bCol;
        cp_async16(smem_u32(&sm[base + 5120 + kr * 136 + bCol]), &g_Bhi[off], 16);
        cp_async16(smem_u32(&sm[base + 7296 + kr * 136 + bCol]), &g_Blo[off], 16);
    }
    cp_commit();
}

__global__ __launch_bounds__(256, 2)
void k_gemm_tf32() {
    extern __shared__ uint32_t sm[];
    int tid  = threadIdx.x;
    int lane = tid & 31;
    int warp = tid >> 5;
    int warp_m = (warp & 1) * 64;
    int warp_n = (warp >> 1) * 32;
    int rowBase = blockIdx.y * 128;
    int colBase = blockIdx.x * 128;

    int aRow = tid >> 2, aKg = (tid & 3) << 2;
    int bK   = tid >> 5, bCol = (tid & 31) << 2;

    float acc[4][4][4];
#pragma unroll
    for (int i = 0; i < 4; i++)
#pragma unroll
        for (int j = 0; j < 4; j++)
#pragma unroll
            for (int k = 0; k < 4; k++) acc[i][j][k] = 0.f;

    gemm_stage(sm, 0, 0, rowBase, colBase, aRow, aKg, bK, bCol);

    for (int t = 0; t < 32; t++) {
        if (t < 31) {
            gemm_stage(sm, (t + 1) & 1, (t + 1) * 16, rowBase, colBase, aRow, aKg, bK, bCol);
            cp_wait<1>();
        } else {
            cp_wait<0>();
        }
        __syncthreads();

        uint32_t aB = (uint32_t)(t & 1) * GEMM_BUF;
        uint32_t bB = aB + 5120;
#pragma unroll
        for (int k8 = 0; k8 < 16; k8 += 8) {
            uint32_t bh[4][2], bl[4][2];
#pragma unroll
            for (int nt = 0; nt < 4; nt++) {
                int cc = warp_n + nt * 8 + (lane >> 2);
                bh[nt][0] = sm[bB + (k8 + (lane & 3)) * 136 + cc];
                bh[nt][1] = sm[bB + (k8 + 4 + (lane & 3)) * 136 + cc];
                bl[nt][0] = sm[bB + 2176 + (k8 + (lane & 3)) * 136 + cc];
                bl[nt][1] = sm[bB + 2176 + (k8 + 4 + (lane & 3)) * 136 + cc];
            }
#pragma unroll
            for (int mt = 0; mt < 4; mt++) {
                int r0 = warp_m + mt * 16 + (lane >> 2);
                uint32_t ah[4], al[4];
                ah[0] = sm[aB + r0 * 20 + k8 + (lane & 3)];
                ah[1] = sm[aB + (r0 + 8) * 20 + k8 + (lane & 3)];
                ah[2] = sm[aB + r0 * 20 + k8 + 4 + (lane & 3)];
                ah[3] = sm[aB + (r0 + 8) * 20 + k8 + 4 + (lane & 3)];
                al[0] = sm[aB + 2560 + r0 * 20 + k8 + (lane & 3)];
                al[1] = sm[aB + 2560 + (r0 + 8) * 20 + k8 + (lane & 3)];
                al[2] = sm[aB + 2560 + r0 * 20 + k8 + 4 + (lane & 3)];
                al[3] = sm[aB + 2560 + (r0 + 8) * 20 + k8 + 4 + (lane & 3)];
#pragma unroll
                for (int nt = 0; nt < 4; nt++) {
                    mma_tf32(acc[mt][nt], ah, bh[nt]);   // hi*hi
                    mma_tf32(acc[mt][nt], ah, bl[nt]);   // hi*lo
                    mma_tf32(acc[mt][nt], al, bh[nt]);   // lo*hi
                }
            }
        }
        __syncthreads();
    }

#pragma unroll
    for (int mt = 0; mt < 4; mt++) {
        int gr0 = rowBase + warp_m + mt * 16 + (lane >> 2);
#pragma unroll
        for (int nt = 0; nt < 4; nt++) {
            int col = colBase + warp_n + nt * 8 + (lane & 3) * 2;
            if (gr0 < NN)
                *(float2*)&g_hp[(size_t)gr0 * 512 + col] = make_float2(acc[mt][nt][0], acc[mt][nt][1]);
            if (gr0 + 8 < NN)
                *(float2*)&g_hp[(size_t)(gr0 + 8) * 512 + col] = make_float2(acc[mt][nt][2], acc[mt][nt][3]);
        }
    }
}

// ---------------- attention coefficients s,d : [N,8] ----------------
__global__ void k_attn_coef(const float* __restrict__ asrc, const float* __restrict__ adst) {
    int g = blockIdx.x * blockDim.x + threadIdx.x;
    int n = g >> 5, lane = g & 31;
    if (n >= NN) return;
    int c0 = lane * 16;
    const float* row = &g_hp[(size_t)n * 512 + c0];
    float ps = 0.f, pd = 0.f;
#pragma unroll
    for (int u = 0; u < 16; u += 4) {
        float4 v = *(const float4*)&row[u];
        float4 a = *(const float4*)&asrc[c0 + u];
        float4 b = *(const float4*)&adst[c0 + u];
        ps += v.x * a.x + v.y * a.y + v.z * a.z + v.w * a.w;
        pd += v.x * b.x + v.y * b.y + v.z * b.z + v.w * b.w;
    }
    ps += __shfl_down_sync(0xffffffffu, ps, 2);
    pd += __shfl_down_sync(0xffffffffu, pd, 2);
    ps += __shfl_down_sync(0xffffffffu, ps, 1);
    pd += __shfl_down_sync(0xffffffffu, pd, 1);
    if ((lane & 3) == 0) {
        g_s[n * 8 + (lane >> 2)] = ps;
        g_d[n * 8 + (lane >> 2)] = pd;
    }
}

// ---------------- single-pass GAT aggregation (warp per node, raw exp) ---------
// mode 0: write hi/lo (next layer GEMM input); mode 1: write f32 g_hn (heads)
__global__ void k_gat_agg2(const float* __restrict__ bias, int mode) {
    int g = blockIdx.x * blockDim.x + threadIdx.x;
    int n = g >> 5, lane = g & 31;
    if (n >= NN) return;
    int start = g_off[n], end = g_off[n + 1];
    int h8 = lane & 7;
    float dval = g_d[n * 8 + h8];

    float den = 0.f;
    float acc[16];
#pragma unroll
    for (int i = 0; i < 16; i++) acc[i] = 0.f;

#pragma unroll 2
    for (int j = start; j < end; j++) {
        int sj = __ldg(&g_csr[j]);
        float e = __ldg(&g_s[sj * 8 + h8]) + dval;
        e = (e > 0.f) ? e : NEG * e;
        float w = __expf(e);                   // unnormalized; |e| bounded, no overflow
        den += w;
        const float4* row = (const float4*)&g_hp[(size_t)sj * 512];
#pragma unroll
        for (int i = 0; i < 4; i++) {
            int hh = i * 2 + (lane >> 4);      // head owning this lane's float4
            float wi = __shfl_sync(0xffffffffu, w, hh);
            float4 v = __ldg(&row[i * 32 + lane]);
            acc[i * 4 + 0] += wi * v.x;
            acc[i * 4 + 1] += wi * v.y;
            acc[i * 4 + 2] += wi * v.z;
            acc[i * 4 + 3] += wi * v.w;
        }
    }

#pragma unroll
    for (int i = 0; i < 4; i++) {
        int hh = i * 2 + (lane >> 4);
        float dh  = __shfl_sync(0xffffffffu, den, hh);   // lane hh holds head hh's den
        float inv = 1.f / (dh + 1e-16f);
        int col = i * 128 + lane * 4;
        float4 b = *(const float4*)&bias[col];
        float4 o;
        o.x = fmaxf(acc[i * 4 + 0] * inv + b.x, 0.f);
        o.y = fmaxf(acc[i * 4 + 1] * inv + b.y, 0.f);
        o.z = fmaxf(acc[i * 4 + 2] * inv + b.z, 0.f);
        o.w = fmaxf(acc[i * 4 + 3] * inv + b.w, 0.f);
        if (mode) {
            *(float4*)&g_hn[(size_t)n * 512 + col] = o;
        } else {
            uint4 h, l;
            split_tf32(o.x, h.x, l.x);
            split_tf32(o.y, h.y, l.y);
            split_tf32(o.z, h.z, l.z);
            split_tf32(o.w, h.w, l.w);
            *(uint4*)&g_Ahi[(size_t)n * 512 + col] = h;
            *(uint4*)&g_Alo[(size_t)n * 512 + col] = l;
        }
    }
}

// ---------------- attention_weights head: softmax(h @ W_att + b) ----------------
__global__ void k_attw_sel(const float* __restrict__ W, const float* __restrict__ b,
                           float* __restrict__ out) {
    const float* h = g_hn;
    int g = blockIdx.x * blockDim.x + threadIdx.x;
    int n = g >> 5, lane = g & 31;
    if (n >= NN) return;
    int c0 = lane * 16;
    float p[8] = {0, 0, 0, 0, 0, 0, 0, 0};
#pragma unroll
    for (int u = 0; u < 16; u++) {
        float v = h[(size_t)n * 512 + c0 + u];
        float4 w0 = *(const float4*)&W[(c0 + u) * 8];
        float4 w1 = *(const float4*)&W[(c0 + u) * 8 + 4];
        p[0] += v * w0.x; p[1] += v * w0.y; p[2] += v * w0.z; p[3] += v * w0.w;
        p[4] += v * w1.x; p[5] += v * w1.y; p[6] += v * w1.z; p[7] += v * w1.w;
    }
#pragma unroll
    for (int o = 16; o; o >>= 1)
#pragma unroll
        for (int hh = 0; hh < 8; hh++) p[hh] += __shfl_xor_sync(0xffffffffu, p[hh], o);
    if (lane == 0) {
        float mx = -1e30f;
#pragma unroll
        for (int hh = 0; hh < 8; hh++) { p[hh] += b[hh]; mx = fmaxf(mx, p[hh]); }
        float sum = 0.f;
#pragma unroll
        for (int hh = 0; hh < 8; hh++) { p[hh] = __expf(p[hh] - mx); sum += p[hh]; }
        float is = 1.f / sum;
#pragma unroll
        for (int hh = 0; hh < 8; hh++) out[n * 8 + hh] = p[hh] * is;
    }
}

// ---------------- anomaly head: sigmoid(relu(h@W1+b1)@W2+b2) ----------------
__global__ __launch_bounds__(512)
void k_anomaly_sel(const float* __restrict__ W1, const float* __restrict__ b1,
                   const float* __restrict__ W2, const float* __restrict__ b2,
                   float* __restrict__ out) {
    const float* h = g_hn;
    __shared__ float hs[8][516];
    __shared__ float Ws[64][68];
    __shared__ float wsum[16];
    int tid = threadIdx.x;
    int n0 = blockIdx.x * 8;
#pragma unroll
    for (int sidx = 0; sidx < 8; sidx++) {
        int idx = sidx * 512 + tid;
        int rr = idx >> 9, cc = idx & 511;
        int n = n0 + rr;
        hs[rr][cc] = (n < NN) ? h[(size_t)n * 512 + cc] : 0.f;
    }
    int r = tid >> 6, c = tid & 63;
    float acc = 0.f;
    for (int k0 = 0; k0 < 512; k0 += 64) {
        __syncthreads();
#pragma unroll
        for (int sidx = 0; sidx < 8; sidx++) {
            int idx = sidx * 512 + tid;
            int kk = idx >> 6, cc2 = idx & 63;
            Ws[kk][cc2] = W1[(k0 + kk) * 64 + cc2];
        }
        __syncthreads();
#pragma unroll 16
        for (int k = 0; k < 64; k++) acc += hs[r][k0 + k] * Ws[k][c];
    }
    float t = fmaxf(acc + b1[c], 0.f);
    float part = t * W2[c];
#pragma unroll
    for (int o = 16; o; o >>= 1) part += __shfl_xor_sync(0xffffffffu, part, o);
    if ((tid & 31) == 0) wsum[tid >> 5] = part;
    __syncthreads();
    if ((tid & 63) == 0) {
        float sum = wsum[tid >> 5] + wsum[(tid >> 5) + 1];
        int n = n0 + r;
        if (n < NN) out[n] = 1.f / (1.f + __expf(-(sum + b2[0])));
    }
}

// ---------------- launch ----------------
extern "C" void kernel_launch(void* const* d_in, const int* in_sizes, int n_in,
                              void* d_out, int out_size) {
    const float* x     = (const float*)d_in[0];
    const int*   ei    = (const int*)  d_in[1];
    const float* W_in  = (const float*)d_in[2];
    const float* b_in  = (const float*)d_in[3];
    const float* W_gat = (const float*)d_in[4];
    const float* a_src = (const float*)d_in[5];
    const float* a_dst = (const float*)d_in[6];
    const float* b_gat = (const float*)d_in[7];
    const float* W_att = (const float*)d_in[8];
    const float* b_att = (const float*)d_in[9];
    const float* W_h1  = (const float*)d_in[10];
    const float* b_h1  = (const float*)d_in[11];
    const float* W_h2  = (const float*)d_in[12];
    const float* b_h2  = (const float*)d_in[13];
    float* out = (float*)d_out;

    // opt-in dynamic smem for the double-buffered GEMM (idempotent, capture-safe)
    static int attr_done = 0;
    if (!attr_done) {
        cudaFuncSetAttribute(k_gemm_tf32, cudaFuncAttributeMaxDynamicSharedMemorySize,
                             2 * GEMM_BUF * 4);
        attr_done = 1;
    }

    // CSR by destination
    k_init_counts<<<(NN + 255) / 256, 256>>>();
    k_count<<<(EE + 255) / 256, 256>>>(ei);
    k_scan<<<1, 1024>>>();
    k_scatter<<<(EPLUS + 255) / 256, 256>>>(ei);

    // input projection -> hi/lo activations
    k_input_proj<<<(NN + 7) / 8, 512>>>(x, W_in, b_in);

    // 3 GAT layers
    dim3 grid(4, (NN + 127) / 128);
    for (int l = 0; l < 3; l++) {
        k_convB<<<256, 256>>>(W_gat + (size_t)l * 512 * 512);
        k_gemm_tf32<<<grid, 256, 2 * GEMM_BUF * 4>>>();
        k_attn_coef<<<(NN * 32 + 255) / 256, 256>>>(a_src + l * 512, a_dst + l * 512);
        k_gat_agg2<<<(NN * 32 + 255) / 256, 256>>>(b_gat + l * 512, (l == 2) ? 1 : 0);
    }

    // heads: out[0:N) = anomaly scores, out[N:N+8N) = attention weights
    k_attw_sel<<<(NN * 32 + 255) / 256, 256>>>(W_att, b_att, out + NN);
    k_anomaly_sel<<<(NN + 7) / 8, 512>>>(W_h1, b_h1, W_h2, b_h2, out);
}

// round 9
// speedup vs baseline: 1.4690x; 1.2321x over previous
#include <cuda_runtime.h>
#include <cuda_fp16.h>
#include <math.h>
#include <stdint.h>

#define NN 30000
#define EE 480000
#define EPLUS (EE + NN)
#define NEG 0.2f

// ---------------- scratch (static device globals; no allocation) ----------------
__device__ float  g_hn[(size_t)NN * 512];   // final-layer f32 (heads input)
__device__ float  g_hp[(size_t)NN * 512];   // per-layer GEMM output (f32)
__device__ __half g_Ah[(size_t)NN * 512];   // activations fp16 hi
__device__ __half g_Al[(size_t)NN * 512];   // activations fp16 lo
__device__ __half g_Bh[512 * 512];          // weights fp16 hi, [N][K] (transposed, K-major)
__device__ __half g_Bl[512 * 512];          // weights fp16 lo
__device__ float  g_s [NN * 8];
__device__ float  g_d [NN * 8];
__device__ int    g_off[NN + 1];
__device__ int    g_cnt[NN];
__device__ int    g_cur[NN];
__device__ int    g_csr[EPLUS];

// ---------------- helpers ----------------
__device__ __forceinline__ uint32_t smem_u32(const void* p) {
    return (uint32_t)__cvta_generic_to_shared(p);
}
__device__ __forceinline__ void cp_async16(uint32_t dst, const void* src, int src_bytes) {
    asm volatile("cp.async.cg.shared.global [%0], [%1], 16, %2;\n"
                 :: "r"(dst), "l"(src), "r"(src_bytes));
}
__device__ __forceinline__ void cp_commit() { asm volatile("cp.async.commit_group;\n"); }
template <int N>
__device__ __forceinline__ void cp_wait() { asm volatile("cp.async.wait_group %0;\n" :: "n"(N)); }

__device__ __forceinline__ void f16_split(float v, __half& hi, __half& lo) {
    hi = __float2half_rn(v);
    lo = __float2half_rn(v - __half2float(hi));
}

// fp16 mma m16n8k16, f32 accumulate
__device__ __forceinline__ void mma_f16(float* c, const uint32_t* a, const uint32_t* b) {
    asm volatile(
        "mma.sync.aligned.m16n8k16.row.col.f32.f16.f16.f32 "
        "{%0,%1,%2,%3}, {%4,%5,%6,%7}, {%8,%9}, {%0,%1,%2,%3};\n"
        : "+f"(c[0]), "+f"(c[1]), "+f"(c[2]), "+f"(c[3])
        : "r"(a[0]), "r"(a[1]), "r"(a[2]), "r"(a[3]), "r"(b[0]), "r"(b[1]));
}

// ---------------- CSR build ----------------
__global__ void k_init_counts() {
    int i = blockIdx.x * blockDim.x + threadIdx.x;
    if (i < NN) { g_cnt[i] = 1; g_cur[i] = 0; }
}

__global__ void k_count(const int* __restrict__ ei) {
    int i = blockIdx.x * blockDim.x + threadIdx.x;
    if (i < EE) atomicAdd(&g_cnt[ei[EE + i]], 1);
}

__global__ void k_scan() {
    __shared__ int sh[1024];
    __shared__ int carry;
    int tid = threadIdx.x;
    if (tid == 0) { carry = 0; g_off[0] = 0; }
    __syncthreads();
    for (int base = 0; base < NN; base += 1024) {
        int i = base + tid;
        int v = (i < NN) ? g_cnt[i] : 0;
        sh[tid] = v;
        __syncthreads();
        for (int o = 1; o < 1024; o <<= 1) {
            int t = (tid >= o) ? sh[tid - o] : 0;
            __syncthreads();
            sh[tid] += t;
            __syncthreads();
        }
        int inc = sh[tid] + carry;
        if (i < NN) g_off[i + 1] = inc;
        __syncthreads();
        if (tid == 1023) carry = inc;
        __syncthreads();
    }
}

__global__ void k_scatter(const int* __restrict__ ei) {
    int i = blockIdx.x * blockDim.x + threadIdx.x;
    if (i < EE) {
        int dst = ei[EE + i], src = ei[i];
        int p = atomicAdd(&g_cur[dst], 1);
        g_csr[g_off[dst] + p] = src;
    } else if (i < EPLUS) {
        int n = i - EE;
        int p = atomicAdd(&g_cur[n], 1);
        g_csr[g_off[n] + p] = n;
    }
}

// ---------------- input projection: relu(x @ W_in + b) -> fp16 hi/lo ------------
__global__ void k_input_proj(const float* __restrict__ x, const float* __restrict__ W,
                             const float* __restrict__ b) {
    __shared__ float xs[8][32];
    int j  = threadIdx.x;
    int n0 = blockIdx.x * 8;
    if (j < 256) {
        int r = j >> 5, c = j & 31, n = n0 + r;
        xs[r][c] = (n < NN) ? x[n * 32 + c] : 0.f;
    }
    __syncthreads();
    float acc[8] = {0, 0, 0, 0, 0, 0, 0, 0};
#pragma unroll 8
    for (int k = 0; k < 32; k++) {
        float w = W[k * 512 + j];
#pragma unroll
        for (int r = 0; r < 8; r++) acc[r] += xs[r][k] * w;
    }
    float bb = b[j];
#pragma unroll
    for (int r = 0; r < 8; r++) {
        int n = n0 + r;
        if (n < NN) {
            float v = fmaxf(acc[r] + bb, 0.f);
            __half hi, lo;
            f16_split(v, hi, lo);
            g_Ah[(size_t)n * 512 + j] = hi;
            g_Al[(size_t)n * 512 + j] = lo;
        }
    }
}

// ---------------- weight conv: W[K][N] f32 -> transposed fp16 hi/lo [N][K] ------
__global__ void k_convB(const float* __restrict__ W) {
    int id = blockIdx.x * blockDim.x + threadIdx.x;  // 0..65535
    int n  = id >> 7;
    int k0 = (id & 127) * 4;
#pragma unroll
    for (int i = 0; i < 4; i++) {
        float v = __ldg(&W[(size_t)(k0 + i) * 512 + n]);
        __half hi, lo;
        f16_split(v, hi, lo);
        g_Bh[n * 512 + k0 + i] = hi;
        g_Bl[n * 512 + k0 + i] = lo;
    }
}

// ---------------- fp16-split tensor GEMM: g_hp = A[NN,512] @ B[512,512] ---------
// CTA 128x128, 8 warps (2x4), warp tile 64x32, k-tile 16, double-buffered cp.async.
// smem per buffer (halfs, stride 24 = conflict-free):
//   A_hi [128][24] @0, A_lo @3072, B_hi [128][24] @6144, B_lo @9216 -> 12288 halfs
#define GBUF 12288

__device__ __forceinline__ void stage16(__half* sm, int buf, int k0, int rowBase,
                                        int colBase, int r, int c) {
    // r = row 0..127, c = 0/1 selecting 8-half chunk
    uint32_t base = buf * GBUF;
    uint32_t dA = smem_u32(&sm[base + r * 24 + c * 8]);
    int gr = rowBase + r;
    int sz = (gr < NN) ? 16 : 0;
    size_t aoff = (size_t)(gr < NN ? gr : NN - 1) * 512 + k0 + c * 8;
    cp_async16(dA, &g_Ah[aoff], sz);
    cp_async16(smem_u32(&sm[base + 3072 + r * 24 + c * 8]), &g_Al[aoff], sz);
    size_t boff = (size_t)(colBase + r) * 512 + k0 + c * 8;
    cp_async16(smem_u32(&sm[base + 6144 + r * 24 + c * 8]), &g_Bh[boff], 16);
    cp_async16(smem_u32(&sm[base + 9216 + r * 24 + c * 8]), &g_Bl[boff], 16);
}

__global__ __launch_bounds__(256, 2)
void k_gemm_f16() {
    extern __shared__ __half sm[];
    int tid  = threadIdx.x;
    int lane = tid & 31;
    int warp = tid >> 5;
    int warp_m = (warp & 1) * 64;
    int warp_n = (warp >> 1) * 32;
    int rowBase = blockIdx.y * 128;
    int colBase = blockIdx.x * 128;

    int ldr = tid >> 1, ldc = tid & 1;

    float acc[4][4][4];
#pragma unroll
    for (int i = 0; i < 4; i++)
#pragma unroll
        for (int j = 0; j < 4; j++)
#pragma unroll
            for (int k = 0; k < 4; k++) acc[i][j][k] = 0.f;

    stage16(sm, 0, 0, rowBase, colBase, ldr, ldc);
    cp_commit();

    for (int t = 0; t < 32; t++) {
        if (t < 31) {
            stage16(sm, (t + 1) & 1, (t + 1) * 16, rowBase, colBase, ldr, ldc);
            cp_commit();
            cp_wait<1>();
        } else {
            cp_wait<0>();
        }
        __syncthreads();

        const __half* A_hi = &sm[(t & 1) * GBUF];
        const __half* A_lo = A_hi + 3072;
        const __half* B_hi = A_hi + 6144;
        const __half* B_lo = A_hi + 9216;

        uint32_t bh[4][2], bl[4][2];
#pragma unroll
        for (int nt = 0; nt < 4; nt++) {
            int n0 = warp_n + nt * 8 + (lane >> 2);
            bh[nt][0] = *(const uint32_t*)&B_hi[n0 * 24 + (lane & 3) * 2];
            bh[nt][1] = *(const uint32_t*)&B_hi[n0 * 24 + 8 + (lane & 3) * 2];
            bl[nt][0] = *(const uint32_t*)&B_lo[n0 * 24 + (lane & 3) * 2];
            bl[nt][1] = *(const uint32_t*)&B_lo[n0 * 24 + 8 + (lane & 3) * 2];
        }
#pragma unroll
        for (int mt = 0; mt < 4; mt++) {
            int r0 = warp_m + mt * 16 + (lane >> 2);
            uint32_t ah[4], al[4];
            ah[0] = *(const uint32_t*)&A_hi[r0 * 24 + (lane & 3) * 2];
            ah[1] = *(const uint32_t*)&A_hi[(r0 + 8) * 24 + (lane & 3) * 2];
            ah[2] = *(const uint32_t*)&A_hi[r0 * 24 + 8 + (lane & 3) * 2];
            ah[3] = *(const uint32_t*)&A_hi[(r0 + 8) * 24 + 8 + (lane & 3) * 2];
            al[0] = *(const uint32_t*)&A_lo[r0 * 24 + (lane & 3) * 2];
            al[1] = *(const uint32_t*)&A_lo[(r0 + 8) * 24 + (lane & 3) * 2];
            al[2] = *(const uint32_t*)&A_lo[r0 * 24 + 8 + (lane & 3) * 2];
            al[3] = *(const uint32_t*)&A_lo[(r0 + 8) * 24 + 8 + (lane & 3) * 2];
#pragma unroll
            for (int nt = 0; nt < 4; nt++) {
                mma_f16(acc[mt][nt], ah, bh[nt]);   // hi*hi
                mma_f16(acc[mt][nt], ah, bl[nt]);   // hi*lo
                mma_f16(acc[mt][nt], al, bh[nt]);   // lo*hi
            }
        }
        __syncthreads();
    }

#pragma unroll
    for (int mt = 0; mt < 4; mt++) {
        int gr0 = rowBase + warp_m + mt * 16 + (lane >> 2);
#pragma unroll
        for (int nt = 0; nt < 4; nt++) {
            int col = colBase + warp_n + nt * 8 + (lane & 3) * 2;
            if (gr0 < NN)
                *(float2*)&g_hp[(size_t)gr0 * 512 + col] = make_float2(acc[mt][nt][0], acc[mt][nt][1]);
            if (gr0 + 8 < NN)
                *(float2*)&g_hp[(size_t)(gr0 + 8) * 512 + col] = make_float2(acc[mt][nt][2], acc[mt][nt][3]);
        }
    }
}

// ---------------- attention coefficients s,d : [N,8] ----------------
__global__ void k_attn_coef(const float* __restrict__ asrc, const float* __restrict__ adst) {
    int g = blockIdx.x * blockDim.x + threadIdx.x;
    int n = g >> 5, lane = g & 31;
    if (n >= NN) return;
    int c0 = lane * 16;
    const float* row = &g_hp[(size_t)n * 512 + c0];
    float ps = 0.f, pd = 0.f;
#pragma unroll
    for (int u = 0; u < 16; u += 4) {
        float4 v = *(const float4*)&row[u];
        float4 a = *(const float4*)&asrc[c0 + u];
        float4 b = *(const float4*)&adst[c0 + u];
        ps += v.x * a.x + v.y * a.y + v.z * a.z + v.w * a.w;
        pd += v.x * b.x + v.y * b.y + v.z * b.z + v.w * b.w;
    }
    ps += __shfl_down_sync(0xffffffffu, ps, 2);
    pd += __shfl_down_sync(0xffffffffu, pd, 2);
    ps += __shfl_down_sync(0xffffffffu, ps, 1);
    pd += __shfl_down_sync(0xffffffffu, pd, 1);
    if ((lane & 3) == 0) {
        g_s[n * 8 + (lane >> 2)] = ps;
        g_d[n * 8 + (lane >> 2)] = pd;
    }
}

// ---------------- single-pass GAT aggregation (warp per node) -------------------
// mode 0: write fp16 hi/lo (next GEMM input); mode 1: write f32 g_hn (heads)
__global__ void k_gat_agg2(const float* __restrict__ bias, int mode) {
    int g = blockIdx.x * blockDim.x + threadIdx.x;
    int n = g >> 5, lane = g & 31;
    if (n >= NN) return;
    int start = g_off[n], end = g_off[n + 1];
    int h8 = lane & 7;
    float dval = g_d[n * 8 + h8];

    float den = 0.f;
    float acc[16];
#pragma unroll
    for (int i = 0; i < 16; i++) acc[i] = 0.f;

#pragma unroll 2
    for (int j = start; j < end; j++) {
        int sj = __ldg(&g_csr[j]);
        float e = __ldg(&g_s[sj * 8 + h8]) + dval;
        e = (e > 0.f) ? e : NEG * e;
        float w = __expf(e);
        den += w;
        const float4* row = (const float4*)&g_hp[(size_t)sj * 512];
#pragma unroll
        for (int i = 0; i < 4; i++) {
            int hh = i * 2 + (lane >> 4);
            float wi = __shfl_sync(0xffffffffu, w, hh);
            float4 v = __ldg(&row[i * 32 + lane]);
            acc[i * 4 + 0] += wi * v.x;
            acc[i * 4 + 1] += wi * v.y;
            acc[i * 4 + 2] += wi * v.z;
            acc[i * 4 + 3] += wi * v.w;
        }
    }

#pragma unroll
    for (int i = 0; i < 4; i++) {
        int hh = i * 2 + (lane >> 4);
        float dh  = __shfl_sync(0xffffffffu, den, hh);
        float inv = 1.f / (dh + 1e-16f);
        int col = i * 128 + lane * 4;
        float4 b = *(const float4*)&bias[col];
        float4 o;
        o.x = fmaxf(acc[i * 4 + 0] * inv + b.x, 0.f);
        o.y = fmaxf(acc[i * 4 + 1] * inv + b.y, 0.f);
        o.z = fmaxf(acc[i * 4 + 2] * inv + b.z, 0.f);
        o.w = fmaxf(acc[i * 4 + 3] * inv + b.w, 0.f);
        if (mode) {
            *(float4*)&g_hn[(size_t)n * 512 + col] = o;
        } else {
            __half hx, lx, hy, ly, hz, lz, hw, lw;
            f16_split(o.x, hx, lx); f16_split(o.y, hy, ly);
            f16_split(o.z, hz, lz); f16_split(o.w, hw, lw);
            __half2 h01 = __halves2half2(hx, hy), h23 = __halves2half2(hz, hw);
            __half2 l01 = __halves2half2(lx, ly), l23 = __halves2half2(lz, lw);
            *(uint2*)&g_Ah[(size_t)n * 512 + col] =
                make_uint2(*(uint32_t*)&h01, *(uint32_t*)&h23);
            *(uint2*)&g_Al[(size_t)n * 512 + col] =
                make_uint2(*(uint32_t*)&l01, *(uint32_t*)&l23);
        }
    }
}

// ---------------- attention_weights head: softmax(h @ W_att + b) ----------------
__global__ void k_attw_sel(const float* __restrict__ W, const float* __restrict__ b,
                           float* __restrict__ out) {
    const float* h = g_hn;
    int g = blockIdx.x * blockDim.x + threadIdx.x;
    int n = g >> 5, lane = g & 31;
    if (n >= NN) return;
    int c0 = lane * 16;
    float p[8] = {0, 0, 0, 0, 0, 0, 0, 0};
#pragma unroll
    for (int u = 0; u < 16; u++) {
        float v = h[(size_t)n * 512 + c0 + u];
        float4 w0 = *(const float4*)&W[(c0 + u) * 8];
        float4 w1 = *(const float4*)&W[(c0 + u) * 8 + 4];
        p[0] += v * w0.x; p[1] += v * w0.y; p[2] += v * w0.z; p[3] += v * w0.w;
        p[4] += v * w1.x; p[5] += v * w1.y; p[6] += v * w1.z; p[7] += v * w1.w;
    }
#pragma unroll
    for (int o = 16; o; o >>= 1)
#pragma unroll
        for (int hh = 0; hh < 8; hh++) p[hh] += __shfl_xor_sync(0xffffffffu, p[hh], o);
    if (lane == 0) {
        float mx = -1e30f;
#pragma unroll
        for (int hh = 0; hh < 8; hh++) { p[hh] += b[hh]; mx = fmaxf(mx, p[hh]); }
        float sum = 0.f;
#pragma unroll
        for (int hh = 0; hh < 8; hh++) { p[hh] = __expf(p[hh] - mx); sum += p[hh]; }
        float is = 1.f / sum;
#pragma unroll
        for (int hh = 0; hh < 8; hh++) out[n * 8 + hh] = p[hh] * is;
    }
}

// ---------------- anomaly head: sigmoid(relu(h@W1+b1)@W2+b2) ----------------
__global__ __launch_bounds__(512)
void k_anomaly_sel(const float* __restrict__ W1, const float* __restrict__ b1,
                   const float* __restrict__ W2, const float* __restrict__ b2,
                   float* __restrict__ out) {
    const float* h = g_hn;
    __shared__ float hs[8][516];
    __shared__ float Ws[64][68];
    __shared__ float wsum[16];
    int tid = threadIdx.x;
    int n0 = blockIdx.x * 8;
#pragma unroll
    for (int sidx = 0; sidx < 8; sidx++) {
        int idx = sidx * 512 + tid;
        int rr = idx >> 9, cc = idx & 511;
        int n = n0 + rr;
        hs[rr][cc] = (n < NN) ? h[(size_t)n * 512 + cc] : 0.f;
    }
    int r = tid >> 6, c = tid & 63;
    float acc = 0.f;
    for (int k0 = 0; k0 < 512; k0 += 64) {
        __syncthreads();
#pragma unroll
        for (int sidx = 0; sidx < 8; sidx++) {
            int idx = sidx * 512 + tid;
            int kk = idx >> 6, cc2 = idx & 63;
            Ws[kk][cc2] = W1[(k0 + kk) * 64 + cc2];
        }
        __syncthreads();
#pragma unroll 16
        for (int k = 0; k < 64; k++) acc += hs[r][k0 + k] * Ws[k][c];
    }
    float t = fmaxf(acc + b1[c], 0.f);
    float part = t * W2[c];
#pragma unroll
    for (int o = 16; o; o >>= 1) part += __shfl_xor_sync(0xffffffffu, part, o);
    if ((tid & 31) == 0) wsum[tid >> 5] = part;
    __syncthreads();
    if ((tid & 63) == 0) {
        float sum = wsum[tid >> 5] + wsum[(tid >> 5) + 1];
        int n = n0 + r;
        if (n < NN) out[n] = 1.f / (1.f + __expf(-(sum + b2[0])));
    }
}

// ---------------- launch ----------------
#define GEMM_SMEM (2 * GBUF * 2)   // 2 buffers * 12288 halfs * 2 bytes = 49152

extern "C" void kernel_launch(void* const* d_in, const int* in_sizes, int n_in,
                              void* d_out, int out_size) {
    const float* x     = (const float*)d_in[0];
    const int*   ei    = (const int*)  d_in[1];
    const float* W_in  = (const float*)d_in[2];
    const float* b_in  = (const float*)d_in[3];
    const float* W_gat = (const float*)d_in[4];
    const float* a_src = (const float*)d_in[5];
    const float* a_dst = (const float*)d_in[6];
    const float* b_gat = (const float*)d_in[7];
    const float* W_att = (const float*)d_in[8];
    const float* b_att = (const float*)d_in[9];
    const float* W_h1  = (const float*)d_in[10];
    const float* b_h1  = (const float*)d_in[11];
    const float* W_h2  = (const float*)d_in[12];
    const float* b_h2  = (const float*)d_in[13];
    float* out = (float*)d_out;

    static int attr_done = 0;
    if (!attr_done) {
        cudaFuncSetAttribute(k_gemm_f16, cudaFuncAttributeMaxDynamicSharedMemorySize,
                             GEMM_SMEM);
        attr_done = 1;
    }

    // CSR by destination
    k_init_counts<<<(NN + 255) / 256, 256>>>();
    k_count<<<(EE + 255) / 256, 256>>>(ei);
    k_scan<<<1, 1024>>>();
    k_scatter<<<(EPLUS + 255) / 256, 256>>>(ei);

    // input projection -> fp16 hi/lo activations
    k_input_proj<<<(NN + 7) / 8, 512>>>(x, W_in, b_in);

    // 3 GAT layers
    dim3 grid(4, (NN + 127) / 128);
    for (int l = 0; l < 3; l++) {
        k_convB<<<256, 256>>>(W_gat + (size_t)l * 512 * 512);
        k_gemm_f16<<<grid, 256, GEMM_SMEM>>>();
        k_attn_coef<<<(NN * 32 + 255) / 256, 256>>>(a_src + l * 512, a_dst + l * 512);
        k_gat_agg2<<<(NN * 32 + 255) / 256, 256>>>(b_gat + l * 512, (l == 2) ? 1 : 0);
    }

    // heads: out[0:N) = anomaly scores, out[N:N+8N) = attention weights
    k_attw_sel<<<(NN * 32 + 255) / 256, 256>>>(W_att, b_att, out + NN);
    k_anomaly_sel<<<(NN + 7) / 8, 512>>>(W_h1, b_h1, W_h2, b_h2, out);
}